// round 11
// baseline (speedup 1.0000x reference)
#include <cuda_runtime.h>
#include <cuda_fp16.h>

#define KB    4
#define RPTS  16384
#define KAPPA 32
#define NX    3
#define NF    13
#define NIN   16
#define DOUT  64
#define NPTS  (KB * RPTS)   // 65536
#define MS    72            // padded halves per m_sh row (144B: conflict-free ldmatrix)
#define GS    72            // padded halves per gamma row
#define IS    36            // padded ints per idx_sh row

// 8 MB fp16 scratch: Q[point][64] halves; one 128B line per row.
__device__ uint4 g_Q4[(size_t)NPTS * 8];

// Monotonic grid-barrier counter (never reset; replay-safe).
__device__ unsigned g_count = 0;

__device__ __forceinline__ void grid_barrier() {
    __threadfence();
    __syncthreads();
    if (threadIdx.x == 0) {
        unsigned old = atomicAdd(&g_count, 1u);
        unsigned target = old - (old % gridDim.x) + gridDim.x;
        while ((int)(*(volatile unsigned*)&g_count - target) < 0) { }
        __threadfence();
    }
    __syncthreads();
}

__device__ __forceinline__ unsigned smem_u32(const void* p) {
    return (unsigned)__cvta_generic_to_shared(p);
}

#define LDMATRIX_X4(r0, r1, r2, r3, addr)                                   \
    asm volatile("ldmatrix.sync.aligned.m8n8.x4.shared.b16 {%0,%1,%2,%3}, [%4];" \
        : "=r"(r0), "=r"(r1), "=r"(r2), "=r"(r3) : "r"(addr))

#define LDMATRIX_X4_T(r0, r1, r2, r3, addr)                                 \
    asm volatile("ldmatrix.sync.aligned.m8n8.x4.trans.shared.b16 {%0,%1,%2,%3}, [%4];" \
        : "=r"(r0), "=r"(r1), "=r"(r2), "=r"(r3) : "r"(addr))

#define MMA_16816(c, a0, a1, a2, a3, b0, b1)                                \
    asm volatile("mma.sync.aligned.m16n8k16.row.col.f32.f16.f16.f32 "       \
        "{%0,%1,%2,%3}, {%4,%5,%6,%7}, {%8,%9}, {%0,%1,%2,%3};"             \
        : "+f"((c)[0]), "+f"((c)[1]), "+f"((c)[2]), "+f"((c)[3])            \
        : "r"(a0), "r"(a1), "r"(a2), "r"(a3), "r"(b0), "r"(b1))

// ---------------------------------------------------------------------------
// Fused persistent kernel.
// Phase 1: Q = P @ H^T -> fp16 g_Q4.   Grid barrier.
// Phase 2: warp-tile = 4 points. For each point the FULL warp walks all 32
//   neighbors with single-row LDG.32 loads (lane l owns dims 2l,2l+1):
//   1 cache line / 1 wavefront per load, zero replays. Running __hmax2 max
//   (init 0 == fused relu), one coalesced STS per point, then m16n64k64 HMMA
//   vs fp16 gamma (fp32 accumulate; garbage rows 4-15 never stored),
//   bias + relu, store rows 0-3.
// ---------------------------------------------------------------------------
__global__ void __launch_bounds__(256, 5) fused_kernel(
    const float* __restrict__ X,      // [NPTS, 3]
    const float* __restrict__ F,      // [NPTS, 13]
    const int*   __restrict__ Nbr,    // [NPTS, 32]
    const float* __restrict__ H,      // [64, 16]
    const float* __restrict__ gamma,  // [64, 64]
    const float* __restrict__ gbias,  // [64]
    float*       __restrict__ out)    // [NPTS, 64]
{
    __shared__ float  Psh[32][17];                      // phase-1 staging
    __shared__ float  Ht[NIN][DOUT];                    // Ht[j][d] = H[d][j]
    __shared__ __align__(16) __half gsh[DOUT][GS];      // fp16 gamma, padded rows
    __shared__ __align__(16) __half m_sh[8][16][MS];    // per-warp maxima (rows 0-3 valid)
    __shared__ __align__(16) int    idx_sh[8][4][IS];   // per-warp 4x32 indices
    __shared__ float  bias_sh[DOUT];

    const int tid = threadIdx.x;

    // ---- one-time staging ----
    for (int i = tid; i < NIN * DOUT; i += 256) {
        int d = i & 63, j = i >> 6;
        Ht[j][d] = H[d * NIN + j];
    }
    for (int i = tid; i < DOUT * DOUT; i += 256) {
        int d = i >> 6, e = i & 63;
        gsh[d][e] = __float2half_rn(gamma[d * DOUT + e]);
    }
    if (tid < DOUT) bias_sh[tid] = gbias[tid];
    // zero the garbage rows of m_sh once (rows 4-15 feed HMMA but are unused)
    for (int i = tid; i < 8 * 16 * (MS / 8); i += 256) {
        *(uint4*)&m_sh[i / (16 * (MS / 8))][(i / (MS / 8)) & 15][(i % (MS / 8)) * 8] =
            make_uint4(0, 0, 0, 0);
    }
    __syncthreads();

    // ================= Phase 1: Q compute =================
    for (int tile = blockIdx.x; tile < NPTS / 32; tile += gridDim.x) {
        const int base = tile * 32;

        __syncthreads();
        if (tid < 96) {
            Psh[tid / 3][tid % 3] = X[(size_t)base * NX + tid];
        }
        for (int i = tid; i < 32 * NF; i += 256) {
            Psh[i / NF][NX + i % NF] = F[(size_t)base * NF + i];
        }
        __syncthreads();

        const int p  = tid >> 3;
        const int c  = tid & 7;
        const int d0 = c * 8;

        float acc[8] = {0.f, 0.f, 0.f, 0.f, 0.f, 0.f, 0.f, 0.f};
#pragma unroll
        for (int j = 0; j < NIN; j++) {
            float pj = Psh[p][j];
            float4 h0 = *(const float4*)&Ht[j][d0];
            float4 h1 = *(const float4*)&Ht[j][d0 + 4];
            acc[0] += pj * h0.x; acc[1] += pj * h0.y;
            acc[2] += pj * h0.z; acc[3] += pj * h0.w;
            acc[4] += pj * h1.x; acc[5] += pj * h1.y;
            acc[6] += pj * h1.z; acc[7] += pj * h1.w;
        }

        __half2 h01 = __floats2half2_rn(acc[0], acc[1]);
        __half2 h23 = __floats2half2_rn(acc[2], acc[3]);
        __half2 h45 = __floats2half2_rn(acc[4], acc[5]);
        __half2 h67 = __floats2half2_rn(acc[6], acc[7]);
        uint4 v;
        v.x = *(unsigned*)&h01; v.y = *(unsigned*)&h23;
        v.z = *(unsigned*)&h45; v.w = *(unsigned*)&h67;
        g_Q4[(size_t)(base + p) * 8 + c] = v;
    }

    // ================= grid barrier =================
    grid_barrier();

    // ================= Phase 2 =================
    const int warp  = tid >> 5;
    const int lane  = tid & 31;
    const int nwarps = gridDim.x * 8;
    const __half2 zero = __float2half2_rn(0.f);

    // ldmatrix lane->address components
    const int mrow  = lane & 15;
    const int mkoff = (lane >> 4) << 3;

    for (int wt = blockIdx.x * 8 + warp; wt < NPTS / 4; wt += nwarps) {
        const int point0 = wt * 4;
        const int k      = point0 >> 14;               // R = 16384
        const __half2* __restrict__ Q2 =
            (const __half2*)(g_Q4 + (size_t)k * RPTS * 8);   // 32 half2 per row

        // stage the 4x32 neighbor indices: one LDG.128 + one STS.128
        __syncwarp();
        uint4 iv = ((const uint4*)(Nbr + (size_t)point0 * KAPPA))[lane];
        *(uint4*)&idx_sh[warp][lane >> 3][(lane & 7) * 4] = iv;
        __syncwarp();

        // ---- gather: full warp per point, LDG.32 single-row loads ----
#pragma unroll
        for (int p = 0; p < 4; p++) {
            const int* __restrict__ row = idx_sh[warp][p];
            __half2 m = zero;
#pragma unroll
            for (int g = 0; g < 8; g++) {
                int4 iq = *(const int4*)&row[g * 4];   // broadcast LDS.128
                __half2 v0 = Q2[(size_t)iq.x * 32 + lane];
                __half2 v1 = Q2[(size_t)iq.y * 32 + lane];
                __half2 v2 = Q2[(size_t)iq.z * 32 + lane];
                __half2 v3 = Q2[(size_t)iq.w * 32 + lane];
                m = __hmax2(m, __hmax2(__hmax2(v0, v1), __hmax2(v2, v3)));
            }
            // park: 32 lanes x 4B consecutive -> 1 wavefront
            *(__half2*)&m_sh[warp][p][2 * lane] = m;
        }
        __syncwarp();

        // ---- HMMA matvec: [16 x 64] = m_sh @ gamma[64 x 64] (rows 0-3 valid) ----
        const int r0 = lane >> 2;          // C row
        const int cc = (lane & 3) * 2;     // C col pair within n-frag
        const bool rvalid = (r0 < 4);      // only rows 0-3 are real points

#pragma unroll
        for (int nh = 0; nh < 2; nh++) {
            float c[4][4];
#pragma unroll
            for (int f = 0; f < 4; f++) {
                float2 bb = *(const float2*)&bias_sh[(nh * 4 + f) * 8 + cc];
                c[f][0] = bb.x; c[f][1] = bb.y;
                c[f][2] = bb.x; c[f][3] = bb.y;
            }

#pragma unroll
            for (int kf = 0; kf < 4; kf++) {
                unsigned a0, a1, a2, a3;
                unsigned aaddr = smem_u32(&m_sh[warp][mrow][kf * 16 + mkoff]);
                LDMATRIX_X4(a0, a1, a2, a3, aaddr);

#pragma unroll
                for (int fq = 0; fq < 2; fq++) {
                    const int n0 = (nh * 4 + fq * 2) * 8;
                    unsigned b0, b1, b2, b3;
                    unsigned baddr = smem_u32(&gsh[kf * 16 + mrow][n0 + mkoff]);
                    LDMATRIX_X4_T(b0, b1, b2, b3, baddr);
                    MMA_16816(c[fq * 2],     a0, a1, a2, a3, b0, b1);
                    MMA_16816(c[fq * 2 + 1], a0, a1, a2, a3, b2, b3);
                }
            }

            if (rvalid) {
#pragma unroll
                for (int f = 0; f < 4; f++) {
                    const int n0 = (nh * 4 + f) * 8;
                    float2 v0 = make_float2(fmaxf(c[f][0], 0.f), fmaxf(c[f][1], 0.f));
                    *(float2*)&out[(size_t)(point0 + r0) * DOUT + n0 + cc] = v0;
                }
            }
        }
    }
}

// ---------------------------------------------------------------------------
extern "C" void kernel_launch(void* const* d_in, const int* in_sizes, int n_in,
                              void* d_out, int out_size)
{
    const float* X     = (const float*)d_in[0];
    const float* F     = (const float*)d_in[1];
    const int*   Nbr   = (const int*)  d_in[2];
    const float* H     = (const float*)d_in[3];
    const float* gamma = (const float*)d_in[4];
    const float* gbias = (const float*)d_in[5];
    float*       out   = (float*)d_out;

    (void)in_sizes; (void)n_in; (void)out_size;

    int dev = 0, sms = 148, maxb = 1;
    cudaGetDevice(&dev);
    cudaDeviceGetAttribute(&sms, cudaDevAttrMultiProcessorCount, dev);
    cudaOccupancyMaxActiveBlocksPerMultiprocessor(&maxb, fused_kernel, 256, 0);
    if (maxb < 1) maxb = 1;
    if (maxb > 8) maxb = 8;
    int blocks = sms * maxb;

    fused_kernel<<<blocks, 256>>>(X, F, Nbr, H, gamma, gbias, out);
}

// round 13
// speedup vs baseline: 1.1191x; 1.1191x over previous
#include <cuda_runtime.h>
#include <cuda_fp16.h>

#define KB    4
#define RPTS  16384
#define KAPPA 32
#define NX    3
#define NF    13
#define NIN   16
#define DOUT  64
#define NPTS  (KB * RPTS)   // 65536
#define MS    72            // padded halves per m_sh row (144B: conflict-free ldmatrix)
#define GS    72            // padded halves per gamma row
#define IS    36            // padded ints per idx_sh row

// 8 MB fp16 scratch: Q[point][64] halves; one 128B line per row.
__device__ uint4 g_Q4[(size_t)NPTS * 8];

// Monotonic grid-barrier counter (never reset; replay-safe).
__device__ unsigned g_count = 0;

__device__ __forceinline__ void grid_barrier() {
    __threadfence();
    __syncthreads();
    if (threadIdx.x == 0) {
        unsigned old = atomicAdd(&g_count, 1u);
        unsigned target = old - (old % gridDim.x) + gridDim.x;
        while ((int)(*(volatile unsigned*)&g_count - target) < 0) { }
        __threadfence();
    }
    __syncthreads();
}

__device__ __forceinline__ unsigned smem_u32(const void* p) {
    return (unsigned)__cvta_generic_to_shared(p);
}

#define LDMATRIX_X4(r0, r1, r2, r3, addr)                                   \
    asm volatile("ldmatrix.sync.aligned.m8n8.x4.shared.b16 {%0,%1,%2,%3}, [%4];" \
        : "=r"(r0), "=r"(r1), "=r"(r2), "=r"(r3) : "r"(addr))

#define LDMATRIX_X4_T(r0, r1, r2, r3, addr)                                 \
    asm volatile("ldmatrix.sync.aligned.m8n8.x4.trans.shared.b16 {%0,%1,%2,%3}, [%4];" \
        : "=r"(r0), "=r"(r1), "=r"(r2), "=r"(r3) : "r"(addr))

#define MMA_16816(c, a0, a1, a2, a3, b0, b1)                                \
    asm volatile("mma.sync.aligned.m16n8k16.row.col.f32.f16.f16.f32 "       \
        "{%0,%1,%2,%3}, {%4,%5,%6,%7}, {%8,%9}, {%0,%1,%2,%3};"             \
        : "+f"((c)[0]), "+f"((c)[1]), "+f"((c)[2]), "+f"((c)[3])            \
        : "r"(a0), "r"(a1), "r"(a2), "r"(a3), "r"(b0), "r"(b1))

// ---------------------------------------------------------------------------
// Fused persistent kernel.
// Phase 1: Q = P @ H^T -> fp16 g_Q4.   Grid barrier.
// Phase 2: warp-tile = 8 points (2 sub-batches of 4). Within a sub-batch the
//   8-lane group rsel owns point (sub*4 + rsel) entirely: it walks all 32 of
//   that point's neighbors via LDG.128 (4 rows / 4 lines per instruction),
//   keeps a complete running max in registers (init 0 == fused relu), parks
//   it with one warp-wide STS.128. Then one m16n64k64 HMMA GEMM vs fp16
//   gamma (fp32 accumulate; zero rows 8-15 never stored), bias+relu, store.
// ---------------------------------------------------------------------------
__global__ void __launch_bounds__(256, 5) fused_kernel(
    const float* __restrict__ X,      // [NPTS, 3]
    const float* __restrict__ F,      // [NPTS, 13]
    const int*   __restrict__ Nbr,    // [NPTS, 32]
    const float* __restrict__ H,      // [64, 16]
    const float* __restrict__ gamma,  // [64, 64]
    const float* __restrict__ gbias,  // [64]
    float*       __restrict__ out)    // [NPTS, 64]
{
    __shared__ float  Psh[32][17];                      // phase-1 staging
    __shared__ float  Ht[NIN][DOUT];                    // Ht[j][d] = H[d][j]
    __shared__ __align__(16) __half gsh[DOUT][GS];      // fp16 gamma, padded rows
    __shared__ __align__(16) __half m_sh[8][16][MS];    // per-warp maxima (rows 0-7 live)
    __shared__ __align__(16) int    idx_sh[8][8][IS];   // per-warp 8x32 indices
    __shared__ float  bias_sh[DOUT];

    const int tid = threadIdx.x;

    // ---- one-time staging ----
    for (int i = tid; i < NIN * DOUT; i += 256) {
        int d = i & 63, j = i >> 6;
        Ht[j][d] = H[d * NIN + j];
    }
    for (int i = tid; i < DOUT * DOUT; i += 256) {
        int d = i >> 6, e = i & 63;
        gsh[d][e] = __float2half_rn(gamma[d * DOUT + e]);
    }
    if (tid < DOUT) bias_sh[tid] = gbias[tid];
    // zero all of m_sh once: rows 8-15 feed HMMA every tile but are never stored
    for (int i = tid; i < 8 * 16 * MS / 8; i += 256) {
        ((uint4*)m_sh)[i] = make_uint4(0, 0, 0, 0);
    }
    __syncthreads();

    // ================= Phase 1: Q compute =================
    for (int tile = blockIdx.x; tile < NPTS / 32; tile += gridDim.x) {
        const int base = tile * 32;

        __syncthreads();
        if (tid < 96) {
            Psh[tid / 3][tid % 3] = X[(size_t)base * NX + tid];
        }
        for (int i = tid; i < 32 * NF; i += 256) {
            Psh[i / NF][NX + i % NF] = F[(size_t)base * NF + i];
        }
        __syncthreads();

        const int p  = tid >> 3;
        const int c  = tid & 7;
        const int d0 = c * 8;

        float acc[8] = {0.f, 0.f, 0.f, 0.f, 0.f, 0.f, 0.f, 0.f};
#pragma unroll
        for (int j = 0; j < NIN; j++) {
            float pj = Psh[p][j];
            float4 h0 = *(const float4*)&Ht[j][d0];
            float4 h1 = *(const float4*)&Ht[j][d0 + 4];
            acc[0] += pj * h0.x; acc[1] += pj * h0.y;
            acc[2] += pj * h0.z; acc[3] += pj * h0.w;
            acc[4] += pj * h1.x; acc[5] += pj * h1.y;
            acc[6] += pj * h1.z; acc[7] += pj * h1.w;
        }

        __half2 h01 = __floats2half2_rn(acc[0], acc[1]);
        __half2 h23 = __floats2half2_rn(acc[2], acc[3]);
        __half2 h45 = __floats2half2_rn(acc[4], acc[5]);
        __half2 h67 = __floats2half2_rn(acc[6], acc[7]);
        uint4 v;
        v.x = *(unsigned*)&h01; v.y = *(unsigned*)&h23;
        v.z = *(unsigned*)&h45; v.w = *(unsigned*)&h67;
        g_Q4[(size_t)(base + p) * 8 + c] = v;
    }

    // ================= grid barrier =================
    grid_barrier();

    // ================= Phase 2 =================
    const int warp  = tid >> 5;
    const int lane  = tid & 31;
    const int chunk = lane & 7;    // 16B chunk of Q row: d = 8*chunk..8*chunk+7
    const int rsel  = lane >> 3;   // which sub-batch point this lane group owns
    const int nwarps = gridDim.x * 8;
    const __half2 zero = __float2half2_rn(0.f);

    // ldmatrix lane->address components
    const int mrow  = lane & 15;
    const int mkoff = (lane >> 4) << 3;

    for (int wt = blockIdx.x * 8 + warp; wt < NPTS / 8; wt += nwarps) {
        const int point0 = wt * 8;
        const int k      = point0 >> 14;               // R = 16384
        const uint4* __restrict__ Qk = g_Q4 + (size_t)k * RPTS * 8;

        // stage all 8x32 neighbor indices up front: 2 LDG.128 + 2 STS.128
        __syncwarp();   // prior tile's idx_sh/m_sh reads complete
        {
            const uint4* nb = (const uint4*)(Nbr + (size_t)point0 * KAPPA);
            uint4 iv0 = nb[lane];
            uint4 iv1 = nb[lane + 32];
            *(uint4*)&idx_sh[warp][lane >> 3][(lane & 7) * 4]       = iv0;
            *(uint4*)&idx_sh[warp][4 + (lane >> 3)][(lane & 7) * 4] = iv1;
        }
        __syncwarp();

        // ---- 2 sub-batches of 4 points: gather + max + park ----
#pragma unroll
        for (int sub = 0; sub < 2; sub++) {
            const int* __restrict__ myrow = idx_sh[warp][sub * 4 + rsel];

            __half2 m0 = zero, m1 = zero, m2 = zero, m3 = zero;
#pragma unroll
            for (int ii = 0; ii < 8; ii++) {
                int4 iq = *(const int4*)&myrow[ii * 4];   // group-broadcast LDS.128
                uint4 v0 = Qk[(size_t)iq.x * 8 + chunk];
                uint4 v1 = Qk[(size_t)iq.y * 8 + chunk];
                uint4 v2 = Qk[(size_t)iq.z * 8 + chunk];
                uint4 v3 = Qk[(size_t)iq.w * 8 + chunk];
                __half2 a0 = __hmax2(*(__half2*)&v0.x, *(__half2*)&v1.x);
                __half2 a1 = __hmax2(*(__half2*)&v0.y, *(__half2*)&v1.y);
                __half2 a2 = __hmax2(*(__half2*)&v0.z, *(__half2*)&v1.z);
                __half2 a3 = __hmax2(*(__half2*)&v0.w, *(__half2*)&v1.w);
                __half2 b0 = __hmax2(*(__half2*)&v2.x, *(__half2*)&v3.x);
                __half2 b1 = __hmax2(*(__half2*)&v2.y, *(__half2*)&v3.y);
                __half2 b2 = __hmax2(*(__half2*)&v2.z, *(__half2*)&v3.z);
                __half2 b3 = __hmax2(*(__half2*)&v2.w, *(__half2*)&v3.w);
                m0 = __hmax2(m0, __hmax2(a0, b0));
                m1 = __hmax2(m1, __hmax2(a1, b1));
                m2 = __hmax2(m2, __hmax2(a2, b2));
                m3 = __hmax2(m3, __hmax2(a3, b3));
            }

            // park: every lane stores its complete 16B chunk of its point
            uint4 mv;
            mv.x = *(unsigned*)&m0; mv.y = *(unsigned*)&m1;
            mv.z = *(unsigned*)&m2; mv.w = *(unsigned*)&m3;
            *(uint4*)&m_sh[warp][sub * 4 + rsel][chunk * 8] = mv;
        }
        __syncwarp();

        // ---- HMMA matvec: [16 x 64] = m_sh @ gamma[64 x 64] (rows 0-7 valid) ----
        const int r0 = lane >> 2;          // C row: 0..7 (all valid for 8-pt tile)
        const int cc = (lane & 3) * 2;     // C col pair within n-frag

#pragma unroll
        for (int nh = 0; nh < 2; nh++) {
            float c[4][4];
#pragma unroll
            for (int f = 0; f < 4; f++) {
                float2 bb = *(const float2*)&bias_sh[(nh * 4 + f) * 8 + cc];
                c[f][0] = bb.x; c[f][1] = bb.y;
                c[f][2] = bb.x; c[f][3] = bb.y;
            }

#pragma unroll
            for (int kf = 0; kf < 4; kf++) {
                unsigned a0, a1, a2, a3;
                unsigned aaddr = smem_u32(&m_sh[warp][mrow][kf * 16 + mkoff]);
                LDMATRIX_X4(a0, a1, a2, a3, aaddr);

#pragma unroll
                for (int fq = 0; fq < 2; fq++) {
                    const int n0 = (nh * 4 + fq * 2) * 8;
                    unsigned b0, b1, b2, b3;
                    unsigned baddr = smem_u32(&gsh[kf * 16 + mrow][n0 + mkoff]);
                    LDMATRIX_X4_T(b0, b1, b2, b3, baddr);
                    MMA_16816(c[fq * 2],     a0, a1, a2, a3, b0, b1);
                    MMA_16816(c[fq * 2 + 1], a0, a1, a2, a3, b2, b3);
                }
            }

            // relu + store (only c[f][0..1] belong to a real row: r0 < 8)
#pragma unroll
            for (int f = 0; f < 4; f++) {
                const int n0 = (nh * 4 + f) * 8;
                float2 v0 = make_float2(fmaxf(c[f][0], 0.f), fmaxf(c[f][1], 0.f));
                *(float2*)&out[(size_t)(point0 + r0) * DOUT + n0 + cc] = v0;
            }
        }
    }
}

// ---------------------------------------------------------------------------
extern "C" void kernel_launch(void* const* d_in, const int* in_sizes, int n_in,
                              void* d_out, int out_size)
{
    const float* X     = (const float*)d_in[0];
    const float* F     = (const float*)d_in[1];
    const int*   Nbr   = (const int*)  d_in[2];
    const float* H     = (const float*)d_in[3];
    const float* gamma = (const float*)d_in[4];
    const float* gbias = (const float*)d_in[5];
    float*       out   = (float*)d_out;

    (void)in_sizes; (void)n_in; (void)out_size;

    int dev = 0, sms = 148, maxb = 1;
    cudaGetDevice(&dev);
    cudaDeviceGetAttribute(&sms, cudaDevAttrMultiProcessorCount, dev);
    cudaOccupancyMaxActiveBlocksPerMultiprocessor(&maxb, fused_kernel, 256, 0);
    if (maxb < 1) maxb = 1;
    if (maxb > 8) maxb = 8;
    int blocks = sms * maxb;

    fused_kernel<<<blocks, 256>>>(X, F, Nbr, H, gamma, gbias, out);
}

// round 14
// speedup vs baseline: 1.2022x; 1.0742x over previous
#include <cuda_runtime.h>
#include <cuda_fp16.h>

#define KB    4
#define RPTS  16384
#define KAPPA 32
#define NX    3
#define NF    13
#define NIN   16
#define DOUT  64
#define NPTS  (KB * RPTS)   // 65536
#define MS    72            // padded halves per m_sh row (144B: conflict-free ldmatrix)
#define GS    72            // padded halves per gamma row
#define IS    36            // padded ints per idx_sh row
#define NTILES (NPTS / 16)  // 4096 phase-2 tiles

// 8 MB fp16 scratch: Q[point][64] halves; one 128B line per row.
__device__ uint4 g_Q4[(size_t)NPTS * 8];

// Monotonic grid-barrier counter (never reset; replay-safe).
__device__ unsigned g_count = 0;
// Phase-2 dynamic tile counter (reset each launch before the barrier).
__device__ unsigned g_tile = 0;

__device__ __forceinline__ void grid_barrier() {
    __threadfence();
    __syncthreads();
    if (threadIdx.x == 0) {
        unsigned old = atomicAdd(&g_count, 1u);
        unsigned target = old - (old % gridDim.x) + gridDim.x;
        while ((int)(*(volatile unsigned*)&g_count - target) < 0) { }
        __threadfence();
    }
    __syncthreads();
}

__device__ __forceinline__ unsigned smem_u32(const void* p) {
    return (unsigned)__cvta_generic_to_shared(p);
}

#define LDMATRIX_X4(r0, r1, r2, r3, addr)                                   \
    asm volatile("ldmatrix.sync.aligned.m8n8.x4.shared.b16 {%0,%1,%2,%3}, [%4];" \
        : "=r"(r0), "=r"(r1), "=r"(r2), "=r"(r3) : "r"(addr))

#define LDMATRIX_X4_T(r0, r1, r2, r3, addr)                                 \
    asm volatile("ldmatrix.sync.aligned.m8n8.x4.trans.shared.b16 {%0,%1,%2,%3}, [%4];" \
        : "=r"(r0), "=r"(r1), "=r"(r2), "=r"(r3) : "r"(addr))

#define MMA_16816(c, a0, a1, a2, a3, b0, b1)                                \
    asm volatile("mma.sync.aligned.m16n8k16.row.col.f32.f16.f16.f32 "       \
        "{%0,%1,%2,%3}, {%4,%5,%6,%7}, {%8,%9}, {%0,%1,%2,%3};"             \
        : "+f"((c)[0]), "+f"((c)[1]), "+f"((c)[2]), "+f"((c)[3])            \
        : "r"(a0), "r"(a1), "r"(a2), "r"(a3), "r"(b0), "r"(b1))

// ---------------------------------------------------------------------------
// Fused persistent kernel (R9 structure + dynamic phase-2 scheduler).
// Phase 1: Q = P @ H^T -> fp16 g_Q4.   Grid barrier (also publishes g_tile=0).
// Phase 2: warps pop 16-point tiles from g_tile. Per tile: 4 sub-batches of
//   4 points; 8-lane group rsel owns point (sub*4+rsel), walks its 32
//   neighbors via LDG.128 (4 rows per instr), running max in regs (init 0 ==
//   fused relu), one STS.128 park. Then m16n64k64 HMMA vs fp16 gamma
//   (fp32 accumulate), bias + relu, store.
// ---------------------------------------------------------------------------
__global__ void __launch_bounds__(256, 4) fused_kernel(
    const float* __restrict__ X,      // [NPTS, 3]
    const float* __restrict__ F,      // [NPTS, 13]
    const int*   __restrict__ Nbr,    // [NPTS, 32]
    const float* __restrict__ H,      // [64, 16]
    const float* __restrict__ gamma,  // [64, 64]
    const float* __restrict__ gbias,  // [64]
    float*       __restrict__ out)    // [NPTS, 64]
{
    __shared__ float  Psh[32][17];                      // phase-1 staging
    __shared__ float  Ht[NIN][DOUT];                    // Ht[j][d] = H[d][j]
    __shared__ __align__(16) __half gsh[DOUT][GS];      // fp16 gamma, padded rows
    __shared__ __align__(16) __half m_sh[8][16][MS];    // per-warp 16x64 maxima
    __shared__ __align__(16) int    idx_sh[8][4][IS];   // per-warp 4x32 indices
    __shared__ float  bias_sh[DOUT];

    const int tid = threadIdx.x;

    // ---- one-time staging ----
    for (int i = tid; i < NIN * DOUT; i += 256) {
        int d = i & 63, j = i >> 6;
        Ht[j][d] = H[d * NIN + j];
    }
    for (int i = tid; i < DOUT * DOUT; i += 256) {
        int d = i >> 6, e = i & 63;
        gsh[d][e] = __float2half_rn(gamma[d * DOUT + e]);
    }
    if (tid < DOUT) bias_sh[tid] = gbias[tid];
    __syncthreads();

    // ================= Phase 1: Q compute =================
    for (int tile = blockIdx.x; tile < NPTS / 32; tile += gridDim.x) {
        const int base = tile * 32;

        __syncthreads();
        if (tid < 96) {
            Psh[tid / 3][tid % 3] = X[(size_t)base * NX + tid];
        }
        for (int i = tid; i < 32 * NF; i += 256) {
            Psh[i / NF][NX + i % NF] = F[(size_t)base * NF + i];
        }
        __syncthreads();

        const int p  = tid >> 3;
        const int c  = tid & 7;
        const int d0 = c * 8;

        float acc[8] = {0.f, 0.f, 0.f, 0.f, 0.f, 0.f, 0.f, 0.f};
#pragma unroll
        for (int j = 0; j < NIN; j++) {
            float pj = Psh[p][j];
            float4 h0 = *(const float4*)&Ht[j][d0];
            float4 h1 = *(const float4*)&Ht[j][d0 + 4];
            acc[0] += pj * h0.x; acc[1] += pj * h0.y;
            acc[2] += pj * h0.z; acc[3] += pj * h0.w;
            acc[4] += pj * h1.x; acc[5] += pj * h1.y;
            acc[6] += pj * h1.z; acc[7] += pj * h1.w;
        }

        __half2 h01 = __floats2half2_rn(acc[0], acc[1]);
        __half2 h23 = __floats2half2_rn(acc[2], acc[3]);
        __half2 h45 = __floats2half2_rn(acc[4], acc[5]);
        __half2 h67 = __floats2half2_rn(acc[6], acc[7]);
        uint4 v;
        v.x = *(unsigned*)&h01; v.y = *(unsigned*)&h23;
        v.z = *(unsigned*)&h45; v.w = *(unsigned*)&h67;
        g_Q4[(size_t)(base + p) * 8 + c] = v;
    }

    // reset the phase-2 tile counter; the barrier publishes it to all blocks
    if (blockIdx.x == 0 && tid == 0) g_tile = 0;

    // ================= grid barrier =================
    grid_barrier();

    // ================= Phase 2 (dynamic tiles) =================
    const int warp  = tid >> 5;
    const int lane  = tid & 31;
    const int chunk = lane & 7;    // 16B chunk of Q row: d = 8*chunk..8*chunk+7
    const int rsel  = lane >> 3;   // which of the 4 sub-batch points this lane owns
    const __half2 zero = __float2half2_rn(0.f);

    // ldmatrix lane->address components
    const int mrow  = lane & 15;
    const int mkoff = (lane >> 4) << 3;

    for (;;) {
        // pop next tile (lane 0), broadcast to the warp
        unsigned wt;
        if (lane == 0) wt = atomicAdd(&g_tile, 1u);
        wt = __shfl_sync(0xffffffffu, wt, 0);
        if (wt >= NTILES) break;

        const int point0 = (int)wt * 16;
        const int k      = point0 >> 14;               // R = 16384
        const uint4* __restrict__ Qk = g_Q4 + (size_t)k * RPTS * 8;

        // ---- 4 sub-batches of 4 points: gather + max + park ----
#pragma unroll
        for (int sub = 0; sub < 4; sub++) {
            __syncwarp();   // idx_sh / m_sh from previous sub|tile fully consumed

            // stage the 4x32 neighbor indices: one LDG.128 + one STS.128
            uint4 iv = ((const uint4*)(Nbr + (size_t)(point0 + sub * 4) * KAPPA))[lane];
            *(uint4*)&idx_sh[warp][lane >> 3][(lane & 7) * 4] = iv;
            __syncwarp();

            const int* __restrict__ myrow = idx_sh[warp][rsel];

            __half2 m0 = zero, m1 = zero, m2 = zero, m3 = zero;
#pragma unroll
            for (int ii = 0; ii < 8; ii++) {
                int4 iq = *(const int4*)&myrow[ii * 4];   // group-broadcast LDS.128
                uint4 v0 = Qk[(size_t)iq.x * 8 + chunk];
                uint4 v1 = Qk[(size_t)iq.y * 8 + chunk];
                uint4 v2 = Qk[(size_t)iq.z * 8 + chunk];
                uint4 v3 = Qk[(size_t)iq.w * 8 + chunk];
                __half2 a0 = __hmax2(*(__half2*)&v0.x, *(__half2*)&v1.x);
                __half2 a1 = __hmax2(*(__half2*)&v0.y, *(__half2*)&v1.y);
                __half2 a2 = __hmax2(*(__half2*)&v0.z, *(__half2*)&v1.z);
                __half2 a3 = __hmax2(*(__half2*)&v0.w, *(__half2*)&v1.w);
                __half2 b0 = __hmax2(*(__half2*)&v2.x, *(__half2*)&v3.x);
                __half2 b1 = __hmax2(*(__half2*)&v2.y, *(__half2*)&v3.y);
                __half2 b2 = __hmax2(*(__half2*)&v2.z, *(__half2*)&v3.z);
                __half2 b3 = __hmax2(*(__half2*)&v2.w, *(__half2*)&v3.w);
                m0 = __hmax2(m0, __hmax2(a0, b0));
                m1 = __hmax2(m1, __hmax2(a1, b1));
                m2 = __hmax2(m2, __hmax2(a2, b2));
                m3 = __hmax2(m3, __hmax2(a3, b3));
            }

            // park: every lane stores its complete 16B chunk of its point
            uint4 mv;
            mv.x = *(unsigned*)&m0; mv.y = *(unsigned*)&m1;
            mv.z = *(unsigned*)&m2; mv.w = *(unsigned*)&m3;
            *(uint4*)&m_sh[warp][sub * 4 + rsel][chunk * 8] = mv;
        }
        __syncwarp();

        // ---- HMMA matvec: [16 x 64] = m_sh @ gamma[64 x 64] ----
        const int r0 = lane >> 2;
        const int cc = (lane & 3) * 2;

#pragma unroll
        for (int nh = 0; nh < 2; nh++) {
            float c[4][4];
#pragma unroll
            for (int f = 0; f < 4; f++) {
                float2 bb = *(const float2*)&bias_sh[(nh * 4 + f) * 8 + cc];
                c[f][0] = bb.x; c[f][1] = bb.y;
                c[f][2] = bb.x; c[f][3] = bb.y;
            }

#pragma unroll
            for (int kf = 0; kf < 4; kf++) {
                unsigned a0, a1, a2, a3;
                unsigned aaddr = smem_u32(&m_sh[warp][mrow][kf * 16 + mkoff]);
                LDMATRIX_X4(a0, a1, a2, a3, aaddr);

#pragma unroll
                for (int fq = 0; fq < 2; fq++) {
                    const int n0 = (nh * 4 + fq * 2) * 8;
                    unsigned b0, b1, b2, b3;
                    unsigned baddr = smem_u32(&gsh[kf * 16 + mrow][n0 + mkoff]);
                    LDMATRIX_X4_T(b0, b1, b2, b3, baddr);
                    MMA_16816(c[fq * 2],     a0, a1, a2, a3, b0, b1);
                    MMA_16816(c[fq * 2 + 1], a0, a1, a2, a3, b2, b3);
                }
            }

#pragma unroll
            for (int f = 0; f < 4; f++) {
                const int n0 = (nh * 4 + f) * 8;
                float2 v0 = make_float2(fmaxf(c[f][0], 0.f), fmaxf(c[f][1], 0.f));
                float2 v1 = make_float2(fmaxf(c[f][2], 0.f), fmaxf(c[f][3], 0.f));
                *(float2*)&out[(size_t)(point0 + r0)     * DOUT + n0 + cc] = v0;
                *(float2*)&out[(size_t)(point0 + r0 + 8) * DOUT + n0 + cc] = v1;
            }
        }
    }
}

// ---------------------------------------------------------------------------
extern "C" void kernel_launch(void* const* d_in, const int* in_sizes, int n_in,
                              void* d_out, int out_size)
{
    const float* X     = (const float*)d_in[0];
    const float* F     = (const float*)d_in[1];
    const int*   Nbr   = (const int*)  d_in[2];
    const float* H     = (const float*)d_in[3];
    const float* gamma = (const float*)d_in[4];
    const float* gbias = (const float*)d_in[5];
    float*       out   = (float*)d_out;

    (void)in_sizes; (void)n_in; (void)out_size;

    int dev = 0, sms = 148, maxb = 1;
    cudaGetDevice(&dev);
    cudaDeviceGetAttribute(&sms, cudaDevAttrMultiProcessorCount, dev);
    cudaOccupancyMaxActiveBlocksPerMultiprocessor(&maxb, fused_kernel, 256, 0);
    if (maxb < 1) maxb = 1;
    if (maxb > 8) maxb = 8;
    int blocks = sms * maxb;

    fused_kernel<<<blocks, 256>>>(X, F, Nbr, H, gamma, gbias, out);
}